// round 12
// baseline (speedup 1.0000x reference)
#include <cuda_runtime.h>
#include <cstdint>
#include <cstddef>

#define NTOK 131072
constexpr size_t NT = (size_t)NTOK;
constexpr size_t OFF_XW    = 0;
constexpr size_t OFF_T     = NT * 256;
constexpr size_t OFF_QKV   = NT * 512;
constexpr size_t OFF_ATTNO = NT * 1280;
constexpr size_t OFF_XW2   = NT * 1536;
constexpr size_t OFF_F     = NT * 1792;
constexpr size_t OFF_H     = NT * 2048;
constexpr size_t OFF_BT_QKV = NT * 3072;           // 768x256
constexpr size_t OFF_BT_OUT = OFF_BT_QKV + 196608; // 256x256
constexpr size_t OFF_BT_W1  = OFF_BT_OUT + 65536;  // 1024x256
constexpr size_t OFF_BT_W2  = OFF_BT_W1 + 262144;  // 256x1024
__device__ float g_scratch[OFF_BT_W2 + 262144];

// K-dimension permutation (within each 8-group): logical b -> ((b&3)<<1)|(b>>2)
// Makes mma fragment pairs (q, q+4) physically adjacent -> LDS.64 fragment loads.
#define PERM8(b) ((((b) & 3) << 1) | (((b) & 7) >> 2))
#define PERMK(k) (((k) & ~7) | PERM8((k) & 7))

__device__ __forceinline__ float rndt(float x) {   // round to tf32, keep as fp32
    uint32_t u; asm("cvt.rna.tf32.f32 %0, %1;" : "=r"(u) : "f"(x));
    return __uint_as_float(u);
}
__device__ __forceinline__ uint32_t smem_u32(const void* p) {
    uint32_t a;
    asm("{.reg .u64 t; cvta.to.shared.u64 t, %1; cvt.u32.u64 %0, t;}" : "=r"(a) : "l"(p));
    return a;
}
__device__ __forceinline__ void cpa16(uint32_t dst, const float* src) {
    asm volatile("cp.async.ca.shared.global [%0], [%1], 16;" :: "r"(dst), "l"(src));
}
__device__ __forceinline__ void mma8(float* d, const uint32_t* a, const uint32_t* b) {
    asm volatile(
        "mma.sync.aligned.m16n8k8.row.col.f32.tf32.tf32.f32 "
        "{%0,%1,%2,%3},{%4,%5,%6,%7},{%8,%9},{%0,%1,%2,%3};"
        : "+f"(d[0]), "+f"(d[1]), "+f"(d[2]), "+f"(d[3])
        : "r"(a[0]), "r"(a[1]), "r"(a[2]), "r"(a[3]), "r"(b[0]), "r"(b[1]));
}

// ------- weight transpose BT[n][permk(k)] = round_tf32(B[k][n]) ----------
__global__ void __launch_bounds__(256) k_transpose(
    const float* __restrict__ B, float* __restrict__ BT, int K, int N)
{
    __shared__ float t[32][33];
    int kb = blockIdx.y * 32, nb = blockIdx.x * 32;
    int tx = threadIdx.x & 31, ty = threadIdx.x >> 5;
    for (int i = ty; i < 32; i += 8) t[i][tx] = B[(size_t)(kb + i) * N + nb + tx];
    __syncthreads();
    int ptx = (tx & 24) | PERM8(tx & 7);
    for (int i = ty; i < 32; i += 8) BT[(size_t)(nb + i) * K + kb + ptx] = rndt(t[tx][i]);
}

// ---------------- gather / scatter NCHW <-> token-major ----------------
__global__ void __launch_bounds__(256) k_gather(const float* __restrict__ x)
{
    __shared__ float sm[256][33];
    int tid = threadIdx.x, bi = blockIdx.x;
    int dc = bi & 7, w1 = (bi >> 3) & 7, wx = (bi >> 6) & 31, b = bi >> 11;
    const float* xb = x + ((size_t)b * 256 + dc * 32) * 65536 + (size_t)(wx * 8 + w1) * 256;
#pragma unroll
    for (int it = 0; it < 32; ++it) sm[tid][it] = xb[(size_t)it * 65536 + tid];
    __syncthreads();
#pragma unroll
    for (int it = 0; it < 32; ++it) {
        int t = it * 8 + (tid >> 5), dd = tid & 31;
        size_t tok = (((size_t)b * 32 + wx) * 32 + (t >> 3)) * 64 + w1 * 8 + (t & 7);
        g_scratch[OFF_XW + tok * 256 + dc * 32 + dd] = sm[t][dd];
    }
}
__global__ void __launch_bounds__(256) k_scatter(float* __restrict__ out)
{
    __shared__ float sm[256][33];
    int tid = threadIdx.x, bi = blockIdx.x;
    int dc = bi & 7, w1 = (bi >> 3) & 7, wx = (bi >> 6) & 31, b = bi >> 11;
#pragma unroll
    for (int it = 0; it < 32; ++it) {
        int t = it * 8 + (tid >> 5), dd = tid & 31;
        size_t tok = (((size_t)b * 32 + wx) * 32 + (t >> 3)) * 64 + w1 * 8 + (t & 7);
        sm[t][dd] = g_scratch[OFF_T + tok * 256 + dc * 32 + dd];
    }
    __syncthreads();
    float* ob = out + ((size_t)b * 256 + dc * 32) * 65536 + (size_t)(wx * 8 + w1) * 256;
#pragma unroll
    for (int it = 0; it < 32; ++it) ob[(size_t)it * 65536 + tid] = sm[tid][it];
}

// ------- LayerNorm (TWO=1: LN2(LN1(x)); TWO=0: single LN)
// output tf32-rounded AND k-permuted (consumed only as GEMM A).
template <int TWO>
__global__ void __launch_bounds__(256) k_ln(
    const float* __restrict__ src, float* __restrict__ dst,
    const float* __restrict__ g1, const float* __restrict__ b1,
    const float* __restrict__ g2, const float* __restrict__ b2)
{
    __shared__ float sm[8192], sg1[256], sb1[256], sg2[256], sb2[256], st1[32][2], st2[32][2];
    int tid = threadIdx.x;
    size_t base = (size_t)blockIdx.x * 8192;
    sg1[tid] = g1[tid]; sb1[tid] = b1[tid];
    if (TWO) { sg2[tid] = g2[tid]; sb2[tid] = b2[tid]; }
#pragma unroll
    for (int it = 0; it < 32; ++it) sm[it * 256 + tid] = src[base + it * 256 + tid];
    __syncthreads();
    int warp = tid >> 5, lane = tid & 31;
#pragma unroll
    for (int j = 0; j < 4; ++j) {
        int tok = warp * 4 + j;
        float s = 0.f, ss = 0.f;
#pragma unroll
        for (int m = 0; m < 8; ++m) {
            float v = sm[tok * 256 + lane + 32 * m]; s += v; ss += v * v;
        }
#pragma unroll
        for (int o = 16; o > 0; o >>= 1) {
            s += __shfl_xor_sync(~0u, s, o); ss += __shfl_xor_sync(~0u, ss, o);
        }
        float m1 = s * (1.f / 256.f), i1 = rsqrtf(ss * (1.f / 256.f) - m1 * m1 + 1e-5f);
        if (lane == 0) { st1[tok][0] = m1; st1[tok][1] = i1; }
        if (TWO) {
            float s2 = 0.f, ss2 = 0.f;
#pragma unroll
            for (int m = 0; m < 8; ++m) {
                int d = lane + 32 * m;
                float u = (sm[tok * 256 + d] - m1) * i1 * sg1[d] + sb1[d];
                s2 += u; ss2 += u * u;
            }
#pragma unroll
            for (int o = 16; o > 0; o >>= 1) {
                s2 += __shfl_xor_sync(~0u, s2, o); ss2 += __shfl_xor_sync(~0u, ss2, o);
            }
            if (lane == 0) {
                float m2 = s2 * (1.f / 256.f);
                st2[tok][0] = m2; st2[tok][1] = rsqrtf(ss2 * (1.f / 256.f) - m2 * m2 + 1e-5f);
            }
        }
    }
    __syncthreads();
    const int ptid = (tid & ~7) | PERM8(tid & 7);
#pragma unroll
    for (int tok = 0; tok < 32; ++tok) {
        float u = (sm[tok * 256 + tid] - st1[tok][0]) * st1[tok][1] * sg1[tid] + sb1[tid];
        if (TWO) u = (u - st2[tok][0]) * st2[tok][1] * sg2[tid] + sb2[tid];
        dst[base + tok * 256 + ptid] = rndt(u);
    }
}

// -------- tf32 mma.sync GEMM: C[M,N]=A[M,K]@B, BT=[N,K], A/B pre-rounded
// and K-PERMUTED (fragment pairs adjacent -> LDS.64).
// tile 128x128, BK=32, 8 warps (warp 32x64), 2-stage cp.async, 2 CTAs/SM.
// EPI: 0 none | 1 +RES | 2 round(gelu(+BIAS)) PERMUTED C | 3 +BIAS+RES
#define GEMM_SMEM 73728
template <int EPI>
__global__ void __launch_bounds__(256, 2) k_gemm_mma(
    const float* __restrict__ A, const float* __restrict__ BT,
    float* __restrict__ C, const float* __restrict__ RES,
    const float* __restrict__ BIAS, int N, int K)
{
    extern __shared__ float smf[];   // 2 stages x (A[128][36] + B[128][36])
    const int tid = threadIdx.x, lane = tid & 31, wid = tid >> 5;
    const int bm = blockIdx.y << 7, bn = blockIdx.x << 7;
    const int wr = wid & 3, wc = wid >> 2;
    const int g = lane >> 2, q = lane & 3;

    const int lrow = tid >> 3, lkq = (tid & 7) << 2;
    const float* ApG = A  + (size_t)(bm + lrow) * K + lkq;
    const float* BpG = BT + (size_t)(bn + lrow) * K + lkq;
    const uint32_t sBase = smem_u32(smf);
    const uint32_t soff = ((uint32_t)lrow * 36 + (uint32_t)lkq) * 4;

    float acc[2][8][4];
#pragma unroll
    for (int i = 0; i < 2; ++i)
#pragma unroll
        for (int j = 0; j < 8; ++j)
#pragma unroll
            for (int e = 0; e < 4; ++e) acc[i][j][e] = 0.f;

    // prefetch chunk 0
#pragma unroll
    for (int it = 0; it < 4; ++it) {
        cpa16(sBase + soff + it * 32 * 36 * 4, ApG + (size_t)(it * 32) * K);
        cpa16(sBase + 18432u + soff + it * 32 * 36 * 4, BpG + (size_t)(it * 32) * K);
    }
    asm volatile("cp.async.commit_group;" ::: "memory");

    const int nc = K >> 5;
    for (int c = 0; c < nc; ++c) {
        if (c + 1 < nc) {
            const int kc = (c + 1) << 5;
            const uint32_t st = sBase + (uint32_t)((c + 1) & 1) * 36864u;
#pragma unroll
            for (int it = 0; it < 4; ++it) {
                cpa16(st + soff + it * 32 * 36 * 4, ApG + (size_t)(it * 32) * K + kc);
                cpa16(st + 18432u + soff + it * 32 * 36 * 4, BpG + (size_t)(it * 32) * K + kc);
            }
            asm volatile("cp.async.commit_group;" ::: "memory");
            asm volatile("cp.async.wait_group 1;" ::: "memory");
        } else {
            asm volatile("cp.async.wait_group 0;" ::: "memory");
        }
        __syncthreads();

        const uint32_t* Ab = (const uint32_t*)(smf + (c & 1) * 9216) + (wr << 5) * 36;
        const uint32_t* Bb = (const uint32_t*)(smf + (c & 1) * 9216 + 4608) + (wc << 6) * 36;
#pragma unroll
        for (int ks = 0; ks < 4; ++ks) {
            const int kb = (ks << 3) + (q << 1);
            uint2 p00 = *(const uint2*)&Ab[(g) * 36 + kb];
            uint2 p01 = *(const uint2*)&Ab[(8 + g) * 36 + kb];
            uint2 p10 = *(const uint2*)&Ab[(16 + g) * 36 + kb];
            uint2 p11 = *(const uint2*)&Ab[(24 + g) * 36 + kb];
            uint32_t af0[4] = {p00.x, p01.x, p00.y, p01.y};
            uint32_t af1[4] = {p10.x, p11.x, p10.y, p11.y};
#pragma unroll
            for (int nt = 0; nt < 8; ++nt) {
                uint2 bp = *(const uint2*)&Bb[(nt * 8 + g) * 36 + kb];
                uint32_t bf[2] = {bp.x, bp.y};
                mma8(acc[0][nt], af0, bf);
                mma8(acc[1][nt], af1, bf);
            }
        }
        __syncthreads();
    }

    // epilogue
#pragma unroll
    for (int mt = 0; mt < 2; ++mt) {
#pragma unroll
        for (int nt = 0; nt < 8; ++nt) {
            int row0 = bm + (wr << 5) + mt * 16 + g;
            int col  = bn + (wc << 6) + nt * 8 + q * 2;
            float v00 = acc[mt][nt][0], v01 = acc[mt][nt][1];
            float v10 = acc[mt][nt][2], v11 = acc[mt][nt][3];
            if (EPI == 2 || EPI == 3) {
                float2 bb = *(const float2*)(BIAS + col);
                v00 += bb.x; v01 += bb.y; v10 += bb.x; v11 += bb.y;
            }
            if (EPI == 1 || EPI == 3) {
                float2 r0 = *(const float2*)(RES + (size_t)row0 * N + col);
                float2 r1 = *(const float2*)(RES + (size_t)(row0 + 8) * N + col);
                v00 += r0.x; v01 += r0.y; v10 += r1.x; v11 += r1.y;
            }
            if (EPI == 2) {
                // gelu, round, and store K-PERMUTED (C feeds the next GEMM as A)
                v00 = rndt(v00 * normcdff(v00)); v01 = rndt(v01 * normcdff(v01));
                v10 = rndt(v10 * normcdff(v10)); v11 = rndt(v11 * normcdff(v11));
                int gb = bn + (wc << 6) + nt * 8;
                int j0 = gb + PERM8(q * 2), j1 = gb + PERM8(q * 2 + 1);
                C[(size_t)row0 * N + j0] = v00;
                C[(size_t)row0 * N + j1] = v01;
                C[(size_t)(row0 + 8) * N + j0] = v10;
                C[(size_t)(row0 + 8) * N + j1] = v11;
            } else {
                *(float2*)(C + (size_t)row0 * N + col)       = make_float2(v00, v01);
                *(float2*)(C + (size_t)(row0 + 8) * N + col) = make_float2(v10, v11);
            }
        }
    }
}

// -------- windowed attention: 2 heads per pass, K transposed in SMEM ----
// Output (OFF_ATTNO) feeds GEMM<1> as A -> stored K-PERMUTED (float4 reorder).
#define ATTN_SMEM 94752
__global__ void __launch_bounds__(256) k_attn(const float* __restrict__ rpb)
{
    extern __shared__ float sa[];
    float* sqb  = sa;           // [hh*2112 + t*33 + d]
    float* skTb = sa + 4224;    // [hh*2176 + d*68 + t]
    float* svb  = sa + 8576;    // [hh*2304 + t*36 + d]
    float* spb  = sa + 13184;   // [hh*4352 + row*68 + col]
    float* srpb = sa + 21888;   // [1800]

    int tid = threadIdx.x;
    size_t tokbase = (size_t)blockIdx.x * 64;
    const float* qkv = g_scratch + OFF_QKV;
    float* outp = g_scratch + OFF_ATTNO;
    for (int i = tid; i < 1800; i += 256) srpb[i] = rpb[i];

    int row = tid >> 2, c = tid & 3;
    int ri = row >> 3, rj = row & 7;
    const float sc = 0.17677669529663687f;

    for (int h = 0; h < 8; h += 2) {
        __syncthreads();
#pragma unroll
        for (int m = 0; m < 4; ++m) {
            int e = m * 256 + tid;
            int t = e >> 4, rem = e & 15;
            int hh = rem >> 3, d4 = (rem & 7) << 2;
            const float* src = qkv + (tokbase + t) * 768 + (h + hh) * 32 + d4;
            float4 q4 = *(const float4*)src;
            float4 k4 = *(const float4*)(src + 256);
            float4 v4 = *(const float4*)(src + 512);
            float* sq = sqb + hh * 2112 + t * 33;
            sq[d4] = q4.x * sc; sq[d4 + 1] = q4.y * sc;
            sq[d4 + 2] = q4.z * sc; sq[d4 + 3] = q4.w * sc;
            float* sk = skTb + hh * 2176;
            sk[(d4 + 0) * 68 + t] = k4.x; sk[(d4 + 1) * 68 + t] = k4.y;
            sk[(d4 + 2) * 68 + t] = k4.z; sk[(d4 + 3) * 68 + t] = k4.w;
            *(float4*)(svb + hh * 2304 + t * 36 + d4) = v4;
        }
        __syncthreads();

#pragma unroll
        for (int hh = 0; hh < 2; ++hh) {
            const float* sq = sqb + hh * 2112 + row * 33;
            const float* sk = skTb + hh * 2176;
            float s[16];
#pragma unroll
            for (int j = 0; j < 16; ++j) s[j] = 0.f;
#pragma unroll
            for (int d = 0; d < 32; ++d) {
                float qv = sq[d];
#pragma unroll
                for (int m = 0; m < 4; ++m) {
                    float4 kk = *(const float4*)(sk + d * 68 + c * 16 + m * 4);
                    s[m * 4] += qv * kk.x; s[m * 4 + 1] += qv * kk.y;
                    s[m * 4 + 2] += qv * kk.z; s[m * 4 + 3] += qv * kk.w;
                }
            }
#pragma unroll
            for (int j = 0; j < 16; ++j) {
                int col = c * 16 + j;
                s[j] += srpb[((ri - (col >> 3) + 7) * 15 + (rj - (col & 7) + 7)) * 8 + h + hh];
            }
            float mx = s[0];
#pragma unroll
            for (int j = 1; j < 16; ++j) mx = fmaxf(mx, s[j]);
            mx = fmaxf(mx, __shfl_xor_sync(~0u, mx, 1));
            mx = fmaxf(mx, __shfl_xor_sync(~0u, mx, 2));
            float sum = 0.f;
#pragma unroll
            for (int j = 0; j < 16; ++j) { s[j] = __expf(s[j] - mx); sum += s[j]; }
            sum += __shfl_xor_sync(~0u, sum, 1);
            sum += __shfl_xor_sync(~0u, sum, 2);
            float inv = 1.f / sum;
            float* sp = spb + hh * 4352 + row * 68;
#pragma unroll
            for (int m = 0; m < 4; ++m)
                *(float4*)(sp + c * 16 + m * 4) =
                    make_float4(s[m * 4] * inv, s[m * 4 + 1] * inv,
                                s[m * 4 + 2] * inv, s[m * 4 + 3] * inv);
        }
        __syncthreads();

#pragma unroll
        for (int hh = 0; hh < 2; ++hh) {
            const float* sp = spb + hh * 4352 + row * 68;
            const float* sv = svb + hh * 2304;
            float o[8];
#pragma unroll
            for (int dd = 0; dd < 8; ++dd) o[dd] = 0.f;
#pragma unroll
            for (int j4 = 0; j4 < 16; ++j4) {
                float4 p4 = *(const float4*)(sp + j4 * 4);
                const float* v0 = sv + (j4 * 4) * 36 + c * 8;
                float4 a0 = *(const float4*)v0,        a1 = *(const float4*)(v0 + 4);
                float4 b0 = *(const float4*)(v0 + 36), b1 = *(const float4*)(v0 + 40);
                float4 c0 = *(const float4*)(v0 + 72), c1 = *(const float4*)(v0 + 76);
                float4 d0 = *(const float4*)(v0 + 108), d1 = *(const float4*)(v0 + 112);
                o[0] += p4.x * a0.x + p4.y * b0.x + p4.z * c0.x + p4.w * d0.x;
                o[1] += p4.x * a0.y + p4.y * b0.y + p4.z * c0.y + p4.w * d0.y;
                o[2] += p4.x * a0.z + p4.y * b0.z + p4.z * c0.z + p4.w * d0.z;
                o[3] += p4.x * a0.w + p4.y * b0.w + p4.z * c0.w + p4.w * d0.w;
                o[4] += p4.x * a1.x + p4.y * b1.x + p4.z * c1.x + p4.w * d1.x;
                o[5] += p4.x * a1.y + p4.y * b1.y + p4.z * c1.y + p4.w * d1.y;
                o[6] += p4.x * a1.z + p4.y * b1.z + p4.z * c1.z + p4.w * d1.z;
                o[7] += p4.x * a1.w + p4.y * b1.w + p4.z * c1.w + p4.w * d1.w;
            }
            // K-permuted store: physical position PERM8(j) gets logical o[j]
            // -> float4 #1 = (o0,o4,o1,o5), #2 = (o2,o6,o3,o7)
            float* dst = outp + (tokbase + row) * 256 + (h + hh) * 32 + c * 8;
            *(float4*)dst =
                make_float4(rndt(o[0]), rndt(o[4]), rndt(o[1]), rndt(o[5]));
            *(float4*)(dst + 4) =
                make_float4(rndt(o[2]), rndt(o[6]), rndt(o[3]), rndt(o[7]));
        }
    }
}

// ---------------- host launcher ----------------
extern "C" void kernel_launch(void* const* d_in, const int* in_sizes, int n_in,
                              void* d_out, int out_size)
{
    const float* x     = (const float*)d_in[0];
    const float* ln1_g = (const float*)d_in[1];
    const float* ln1_b = (const float*)d_in[2];
    const float* ln2_g = (const float*)d_in[3];
    const float* ln2_b = (const float*)d_in[4];
    const float* w_qkv = (const float*)d_in[5];
    const float* w_out = (const float*)d_in[6];
    const float* rpb   = (const float*)d_in[7];
    const float* ln3_g = (const float*)d_in[8];
    const float* ln3_b = (const float*)d_in[9];
    const float* w1    = (const float*)d_in[10];
    const float* b1    = (const float*)d_in[11];
    const float* w2    = (const float*)d_in[12];
    const float* b2    = (const float*)d_in[13];
    float* out = (float*)d_out;

    float* S = nullptr;
    cudaGetSymbolAddress((void**)&S, g_scratch);

    cudaFuncSetAttribute(k_gemm_mma<0>, cudaFuncAttributeMaxDynamicSharedMemorySize, GEMM_SMEM);
    cudaFuncSetAttribute(k_gemm_mma<1>, cudaFuncAttributeMaxDynamicSharedMemorySize, GEMM_SMEM);
    cudaFuncSetAttribute(k_gemm_mma<2>, cudaFuncAttributeMaxDynamicSharedMemorySize, GEMM_SMEM);
    cudaFuncSetAttribute(k_gemm_mma<3>, cudaFuncAttributeMaxDynamicSharedMemorySize, GEMM_SMEM);
    cudaFuncSetAttribute(k_attn, cudaFuncAttributeMaxDynamicSharedMemorySize, ATTN_SMEM);

    // order chosen so the profiled launch (#4) is the qkv GEMM
    k_gather<<<4096, 256>>>(x);                                              // 1
    k_ln<1><<<4096, 256>>>(S + OFF_XW, S + OFF_T, ln1_g, ln1_b, ln2_g, ln2_b); // 2
    k_transpose<<<dim3(24, 8), 256>>>(w_qkv, S + OFF_BT_QKV, 256, 768);      // 3
    k_gemm_mma<0><<<dim3(6, 1024), 256, GEMM_SMEM>>>(                        // 4
        S + OFF_T, S + OFF_BT_QKV, S + OFF_QKV, S, S, 768, 256);
    k_transpose<<<dim3(8, 8), 256>>>(w_out, S + OFF_BT_OUT, 256, 256);       // 5
    k_transpose<<<dim3(32, 8), 256>>>(w1, S + OFF_BT_W1, 256, 1024);         // 6
    k_transpose<<<dim3(8, 32), 256>>>(w2, S + OFF_BT_W2, 1024, 256);         // 7
    k_attn<<<2048, 256, ATTN_SMEM>>>(rpb);                                   // 8
    k_gemm_mma<1><<<dim3(2, 1024), 256, GEMM_SMEM>>>(
        S + OFF_ATTNO, S + OFF_BT_OUT, S + OFF_XW2, S + OFF_XW, S, 256, 256);
    k_ln<0><<<4096, 256>>>(S + OFF_XW2, S + OFF_F, ln3_g, ln3_b, ln3_g, ln3_b);
    k_gemm_mma<2><<<dim3(8, 1024), 256, GEMM_SMEM>>>(
        S + OFF_F, S + OFF_BT_W1, S + OFF_H, S, b1, 1024, 256);
    k_gemm_mma<3><<<dim3(2, 1024), 256, GEMM_SMEM>>>(
        S + OFF_H, S + OFF_BT_W2, S + OFF_T, S + OFF_XW2, b2, 256, 1024);
    k_scatter<<<4096, 256>>>(out);
}

// round 13
// speedup vs baseline: 1.1299x; 1.1299x over previous
#include <cuda_runtime.h>
#include <cstdint>
#include <cstddef>

#define NTOK 131072
constexpr size_t NT = (size_t)NTOK;
constexpr size_t OFF_XW    = 0;
constexpr size_t OFF_T     = NT * 256;
constexpr size_t OFF_QKV   = NT * 512;
constexpr size_t OFF_ATTNO = NT * 1280;
constexpr size_t OFF_XW2   = NT * 1536;
constexpr size_t OFF_F     = NT * 1792;
constexpr size_t OFF_H     = NT * 2048;
constexpr size_t OFF_BT_QKV = NT * 3072;           // 768x256
constexpr size_t OFF_BT_OUT = OFF_BT_QKV + 196608; // 256x256
constexpr size_t OFF_BT_W1  = OFF_BT_OUT + 65536;  // 1024x256
constexpr size_t OFF_BT_W2  = OFF_BT_W1 + 262144;  // 256x1024
__device__ float g_scratch[OFF_BT_W2 + 262144];

__device__ __forceinline__ float rndt(float x) {   // round to tf32, keep as fp32
    uint32_t u; asm("cvt.rna.tf32.f32 %0, %1;" : "=r"(u) : "f"(x));
    return __uint_as_float(u);
}
__device__ __forceinline__ uint32_t smem_u32(const void* p) {
    uint32_t a;
    asm("{.reg .u64 t; cvta.to.shared.u64 t, %1; cvt.u32.u64 %0, t;}" : "=r"(a) : "l"(p));
    return a;
}
// cp.async.cg: bypass L1 (L2-only). With 3-stage smem (221KB/SM) the L1D
// carveout is ~7KB; .ca would thrash it (R11 regression mechanism).
__device__ __forceinline__ void cpa16(uint32_t dst, const float* src) {
    asm volatile("cp.async.cg.shared.global [%0], [%1], 16;" :: "r"(dst), "l"(src));
}
__device__ __forceinline__ void mma8(float* d, const uint32_t* a, const uint32_t* b) {
    asm volatile(
        "mma.sync.aligned.m16n8k8.row.col.f32.tf32.tf32.f32 "
        "{%0,%1,%2,%3},{%4,%5,%6,%7},{%8,%9},{%0,%1,%2,%3};"
        : "+f"(d[0]), "+f"(d[1]), "+f"(d[2]), "+f"(d[3])
        : "r"(a[0]), "r"(a[1]), "r"(a[2]), "r"(a[3]), "r"(b[0]), "r"(b[1]));
}

// ---------------- weight transpose BT[n][k] = round_tf32(B[k][n]) --------
__global__ void __launch_bounds__(256) k_transpose(
    const float* __restrict__ B, float* __restrict__ BT, int K, int N)
{
    __shared__ float t[32][33];
    int kb = blockIdx.y * 32, nb = blockIdx.x * 32;
    int tx = threadIdx.x & 31, ty = threadIdx.x >> 5;
    for (int i = ty; i < 32; i += 8) t[i][tx] = B[(size_t)(kb + i) * N + nb + tx];
    __syncthreads();
    for (int i = ty; i < 32; i += 8) BT[(size_t)(nb + i) * K + kb + tx] = rndt(t[tx][i]);
}

// ---------------- gather / scatter NCHW <-> token-major ----------------
__global__ void __launch_bounds__(256) k_gather(const float* __restrict__ x)
{
    __shared__ float sm[256][33];
    int tid = threadIdx.x, bi = blockIdx.x;
    int dc = bi & 7, w1 = (bi >> 3) & 7, wx = (bi >> 6) & 31, b = bi >> 11;
    const float* xb = x + ((size_t)b * 256 + dc * 32) * 65536 + (size_t)(wx * 8 + w1) * 256;
#pragma unroll
    for (int it = 0; it < 32; ++it) sm[tid][it] = xb[(size_t)it * 65536 + tid];
    __syncthreads();
#pragma unroll
    for (int it = 0; it < 32; ++it) {
        int t = it * 8 + (tid >> 5), dd = tid & 31;
        size_t tok = (((size_t)b * 32 + wx) * 32 + (t >> 3)) * 64 + w1 * 8 + (t & 7);
        g_scratch[OFF_XW + tok * 256 + dc * 32 + dd] = sm[t][dd];
    }
}
__global__ void __launch_bounds__(256) k_scatter(float* __restrict__ out)
{
    __shared__ float sm[256][33];
    int tid = threadIdx.x, bi = blockIdx.x;
    int dc = bi & 7, w1 = (bi >> 3) & 7, wx = (bi >> 6) & 31, b = bi >> 11;
#pragma unroll
    for (int it = 0; it < 32; ++it) {
        int t = it * 8 + (tid >> 5), dd = tid & 31;
        size_t tok = (((size_t)b * 32 + wx) * 32 + (t >> 3)) * 64 + w1 * 8 + (t & 7);
        sm[t][dd] = g_scratch[OFF_T + tok * 256 + dc * 32 + dd];
    }
    __syncthreads();
    float* ob = out + ((size_t)b * 256 + dc * 32) * 65536 + (size_t)(wx * 8 + w1) * 256;
#pragma unroll
    for (int it = 0; it < 32; ++it) ob[(size_t)it * 65536 + tid] = sm[tid][it];
}

// ------- LayerNorm (TWO=1: LN2(LN1(x)); TWO=0: single LN); tf32-rounds out
template <int TWO>
__global__ void __launch_bounds__(256) k_ln(
    const float* __restrict__ src, float* __restrict__ dst,
    const float* __restrict__ g1, const float* __restrict__ b1,
    const float* __restrict__ g2, const float* __restrict__ b2)
{
    __shared__ float sm[8192], sg1[256], sb1[256], sg2[256], sb2[256], st1[32][2], st2[32][2];
    int tid = threadIdx.x;
    size_t base = (size_t)blockIdx.x * 8192;
    sg1[tid] = g1[tid]; sb1[tid] = b1[tid];
    if (TWO) { sg2[tid] = g2[tid]; sb2[tid] = b2[tid]; }
#pragma unroll
    for (int it = 0; it < 32; ++it) sm[it * 256 + tid] = src[base + it * 256 + tid];
    __syncthreads();
    int warp = tid >> 5, lane = tid & 31;
#pragma unroll
    for (int j = 0; j < 4; ++j) {
        int tok = warp * 4 + j;
        float s = 0.f, ss = 0.f;
#pragma unroll
        for (int m = 0; m < 8; ++m) {
            float v = sm[tok * 256 + lane + 32 * m]; s += v; ss += v * v;
        }
#pragma unroll
        for (int o = 16; o > 0; o >>= 1) {
            s += __shfl_xor_sync(~0u, s, o); ss += __shfl_xor_sync(~0u, ss, o);
        }
        float m1 = s * (1.f / 256.f), i1 = rsqrtf(ss * (1.f / 256.f) - m1 * m1 + 1e-5f);
        if (lane == 0) { st1[tok][0] = m1; st1[tok][1] = i1; }
        if (TWO) {
            float s2 = 0.f, ss2 = 0.f;
#pragma unroll
            for (int m = 0; m < 8; ++m) {
                int d = lane + 32 * m;
                float u = (sm[tok * 256 + d] - m1) * i1 * sg1[d] + sb1[d];
                s2 += u; ss2 += u * u;
            }
#pragma unroll
            for (int o = 16; o > 0; o >>= 1) {
                s2 += __shfl_xor_sync(~0u, s2, o); ss2 += __shfl_xor_sync(~0u, ss2, o);
            }
            if (lane == 0) {
                float m2 = s2 * (1.f / 256.f);
                st2[tok][0] = m2; st2[tok][1] = rsqrtf(ss2 * (1.f / 256.f) - m2 * m2 + 1e-5f);
            }
        }
    }
    __syncthreads();
#pragma unroll
    for (int tok = 0; tok < 32; ++tok) {
        float u = (sm[tok * 256 + tid] - st1[tok][0]) * st1[tok][1] * sg1[tid] + sb1[tid];
        if (TWO) u = (u - st2[tok][0]) * st2[tok][1] * sg2[tid] + sb2[tid];
        dst[base + tok * 256 + tid] = rndt(u);
    }
}

// -------- tf32 mma.sync GEMM: C[M,N]=A[M,K]@B, BT=[N,K], A/B pre-rounded.
// tile 128x128, BK=32, 8 warps (warp 32x64), 3-STAGE cp.async.cg pipeline,
// 128-reg inner loop (R10) -> 2 CTAs/SM. One barrier per chunk.
// EPI: 0 none | 1 +RES | 2 round(gelu(+BIAS)) | 3 +BIAS+RES
#define GEMM_SMEM 110592
template <int EPI>
__global__ void __launch_bounds__(256, 2) k_gemm_mma(
    const float* __restrict__ A, const float* __restrict__ BT,
    float* __restrict__ C, const float* __restrict__ RES,
    const float* __restrict__ BIAS, int N, int K)
{
    extern __shared__ float smf[];   // 3 stages x (A[128][36] + B[128][36])
    const int tid = threadIdx.x, lane = tid & 31, wid = tid >> 5;
    const int bm = blockIdx.y << 7, bn = blockIdx.x << 7;
    const int wr = wid & 3, wc = wid >> 2;
    const int g = lane >> 2, q = lane & 3;

    const int lrow = tid >> 3, lkq = (tid & 7) << 2;
    const float* ApG = A  + (size_t)(bm + lrow) * K + lkq;
    const float* BpG = BT + (size_t)(bn + lrow) * K + lkq;
    const uint32_t sBase = smem_u32(smf);
    const uint32_t soff = ((uint32_t)lrow * 36 + (uint32_t)lkq) * 4;

    float acc[2][8][4];
#pragma unroll
    for (int i = 0; i < 2; ++i)
#pragma unroll
        for (int j = 0; j < 8; ++j)
#pragma unroll
            for (int e = 0; e < 4; ++e) acc[i][j][e] = 0.f;

    const int nc = K >> 5;
    // prologue: stages 0,1
#pragma unroll
    for (int p = 0; p < 2; ++p) {
        const uint32_t st = sBase + (uint32_t)p * 36864u;
        const int kc = p << 5;
#pragma unroll
        for (int it = 0; it < 4; ++it) {
            cpa16(st + soff + it * 32 * 36 * 4, ApG + (size_t)(it * 32) * K + kc);
            cpa16(st + 18432u + soff + it * 32 * 36 * 4, BpG + (size_t)(it * 32) * K + kc);
        }
        asm volatile("cp.async.commit_group;" ::: "memory");
    }

    for (int c = 0; c < nc; ++c) {
        if (c + 1 < nc) asm volatile("cp.async.wait_group 1;" ::: "memory");
        else            asm volatile("cp.async.wait_group 0;" ::: "memory");
        __syncthreads();
        if (c + 2 < nc) {
            const uint32_t st = sBase + (uint32_t)((c + 2) % 3) * 36864u;
            const int kc = (c + 2) << 5;
#pragma unroll
            for (int it = 0; it < 4; ++it) {
                cpa16(st + soff + it * 32 * 36 * 4, ApG + (size_t)(it * 32) * K + kc);
                cpa16(st + 18432u + soff + it * 32 * 36 * 4, BpG + (size_t)(it * 32) * K + kc);
            }
            asm volatile("cp.async.commit_group;" ::: "memory");
        }
        const uint32_t* Ab = (const uint32_t*)(smf + (c % 3) * 9216) + (wr << 5) * 36;
        const uint32_t* Bb = (const uint32_t*)(smf + (c % 3) * 9216 + 4608) + (wc << 6) * 36;
#pragma unroll
        for (int ks = 0; ks < 4; ++ks) {
            const int kb = ks << 3;
            uint32_t af[2][4];
#pragma unroll
            for (int mt = 0; mt < 2; ++mt) {
                af[mt][0] = Ab[(mt * 16 + g) * 36 + kb + q];
                af[mt][1] = Ab[(mt * 16 + 8 + g) * 36 + kb + q];
                af[mt][2] = Ab[(mt * 16 + g) * 36 + kb + 4 + q];
                af[mt][3] = Ab[(mt * 16 + 8 + g) * 36 + kb + 4 + q];
            }
#pragma unroll
            for (int nt = 0; nt < 8; ++nt) {
                uint32_t bf[2];
                bf[0] = Bb[(nt * 8 + g) * 36 + kb + q];
                bf[1] = Bb[(nt * 8 + g) * 36 + kb + 4 + q];
                mma8(acc[0][nt], af[0], bf);
                mma8(acc[1][nt], af[1], bf);
            }
        }
    }

    // epilogue
#pragma unroll
    for (int mt = 0; mt < 2; ++mt) {
#pragma unroll
        for (int nt = 0; nt < 8; ++nt) {
            int row0 = bm + (wr << 5) + mt * 16 + g;
            int col  = bn + (wc << 6) + nt * 8 + q * 2;
            float v00 = acc[mt][nt][0], v01 = acc[mt][nt][1];
            float v10 = acc[mt][nt][2], v11 = acc[mt][nt][3];
            if (EPI == 2 || EPI == 3) {
                float2 bb = *(const float2*)(BIAS + col);
                v00 += bb.x; v01 += bb.y; v10 += bb.x; v11 += bb.y;
            }
            if (EPI == 1 || EPI == 3) {
                float2 r0 = *(const float2*)(RES + (size_t)row0 * N + col);
                float2 r1 = *(const float2*)(RES + (size_t)(row0 + 8) * N + col);
                v00 += r0.x; v01 += r0.y; v10 += r1.x; v11 += r1.y;
            }
            if (EPI == 2) {
                v00 = rndt(v00 * normcdff(v00)); v01 = rndt(v01 * normcdff(v01));
                v10 = rndt(v10 * normcdff(v10)); v11 = rndt(v11 * normcdff(v11));
            }
            *(float2*)(C + (size_t)row0 * N + col)       = make_float2(v00, v01);
            *(float2*)(C + (size_t)(row0 + 8) * N + col) = make_float2(v10, v11);
        }
    }
}

// -------- windowed attention: 2 heads per pass, K transposed in SMEM ----
#define ATTN_SMEM 94752
__global__ void __launch_bounds__(256) k_attn(const float* __restrict__ rpb)
{
    extern __shared__ float sa[];
    float* sqb  = sa;           // [hh*2112 + t*33 + d]
    float* skTb = sa + 4224;    // [hh*2176 + d*68 + t]
    float* svb  = sa + 8576;    // [hh*2304 + t*36 + d]
    float* spb  = sa + 13184;   // [hh*4352 + row*68 + col]
    float* srpb = sa + 21888;   // [1800]

    int tid = threadIdx.x;
    size_t tokbase = (size_t)blockIdx.x * 64;
    const float* qkv = g_scratch + OFF_QKV;
    float* outp = g_scratch + OFF_ATTNO;
    for (int i = tid; i < 1800; i += 256) srpb[i] = rpb[i];

    int row = tid >> 2, c = tid & 3;
    int ri = row >> 3, rj = row & 7;
    const float sc = 0.17677669529663687f;

    for (int h = 0; h < 8; h += 2) {
        __syncthreads();
#pragma unroll
        for (int m = 0; m < 4; ++m) {
            int e = m * 256 + tid;
            int t = e >> 4, rem = e & 15;
            int hh = rem >> 3, d4 = (rem & 7) << 2;
            const float* src = qkv + (tokbase + t) * 768 + (h + hh) * 32 + d4;
            float4 q4 = *(const float4*)src;
            float4 k4 = *(const float4*)(src + 256);
            float4 v4 = *(const float4*)(src + 512);
            float* sq = sqb + hh * 2112 + t * 33;
            sq[d4] = q4.x * sc; sq[d4 + 1] = q4.y * sc;
            sq[d4 + 2] = q4.z * sc; sq[d4 + 3] = q4.w * sc;
            float* sk = skTb + hh * 2176;
            sk[(d4 + 0) * 68 + t] = k4.x; sk[(d4 + 1) * 68 + t] = k4.y;
            sk[(d4 + 2) * 68 + t] = k4.z; sk[(d4 + 3) * 68 + t] = k4.w;
            *(float4*)(svb + hh * 2304 + t * 36 + d4) = v4;
        }
        __syncthreads();

#pragma unroll
        for (int hh = 0; hh < 2; ++hh) {
            const float* sq = sqb + hh * 2112 + row * 33;
            const float* sk = skTb + hh * 2176;
            float s[16];
#pragma unroll
            for (int j = 0; j < 16; ++j) s[j] = 0.f;
#pragma unroll
            for (int d = 0; d < 32; ++d) {
                float qv = sq[d];
#pragma unroll
                for (int m = 0; m < 4; ++m) {
                    float4 kk = *(const float4*)(sk + d * 68 + c * 16 + m * 4);
                    s[m * 4] += qv * kk.x; s[m * 4 + 1] += qv * kk.y;
                    s[m * 4 + 2] += qv * kk.z; s[m * 4 + 3] += qv * kk.w;
                }
            }
#pragma unroll
            for (int j = 0; j < 16; ++j) {
                int col = c * 16 + j;
                s[j] += srpb[((ri - (col >> 3) + 7) * 15 + (rj - (col & 7) + 7)) * 8 + h + hh];
            }
            float mx = s[0];
#pragma unroll
            for (int j = 1; j < 16; ++j) mx = fmaxf(mx, s[j]);
            mx = fmaxf(mx, __shfl_xor_sync(~0u, mx, 1));
            mx = fmaxf(mx, __shfl_xor_sync(~0u, mx, 2));
            float sum = 0.f;
#pragma unroll
            for (int j = 0; j < 16; ++j) { s[j] = __expf(s[j] - mx); sum += s[j]; }
            sum += __shfl_xor_sync(~0u, sum, 1);
            sum += __shfl_xor_sync(~0u, sum, 2);
            float inv = 1.f / sum;
            float* sp = spb + hh * 4352 + row * 68;
#pragma unroll
            for (int m = 0; m < 4; ++m)
                *(float4*)(sp + c * 16 + m * 4) =
                    make_float4(s[m * 4] * inv, s[m * 4 + 1] * inv,
                                s[m * 4 + 2] * inv, s[m * 4 + 3] * inv);
        }
        __syncthreads();

#pragma unroll
        for (int hh = 0; hh < 2; ++hh) {
            const float* sp = spb + hh * 4352 + row * 68;
            const float* sv = svb + hh * 2304;
            float o[8];
#pragma unroll
            for (int dd = 0; dd < 8; ++dd) o[dd] = 0.f;
#pragma unroll
            for (int j4 = 0; j4 < 16; ++j4) {
                float4 p4 = *(const float4*)(sp + j4 * 4);
                const float* v0 = sv + (j4 * 4) * 36 + c * 8;
                float4 a0 = *(const float4*)v0,        a1 = *(const float4*)(v0 + 4);
                float4 b0 = *(const float4*)(v0 + 36), b1 = *(const float4*)(v0 + 40);
                float4 c0 = *(const float4*)(v0 + 72), c1 = *(const float4*)(v0 + 76);
                float4 d0 = *(const float4*)(v0 + 108), d1 = *(const float4*)(v0 + 112);
                o[0] += p4.x * a0.x + p4.y * b0.x + p4.z * c0.x + p4.w * d0.x;
                o[1] += p4.x * a0.y + p4.y * b0.y + p4.z * c0.y + p4.w * d0.y;
                o[2] += p4.x * a0.z + p4.y * b0.z + p4.z * c0.z + p4.w * d0.z;
                o[3] += p4.x * a0.w + p4.y * b0.w + p4.z * c0.w + p4.w * d0.w;
                o[4] += p4.x * a1.x + p4.y * b1.x + p4.z * c1.x + p4.w * d1.x;
                o[5] += p4.x * a1.y + p4.y * b1.y + p4.z * c1.y + p4.w * d1.y;
                o[6] += p4.x * a1.z + p4.y * b1.z + p4.z * c1.z + p4.w * d1.z;
                o[7] += p4.x * a1.w + p4.y * b1.w + p4.z * c1.w + p4.w * d1.w;
            }
            float* dst = outp + (tokbase + row) * 256 + (h + hh) * 32 + c * 8;
            *(float4*)dst =
                make_float4(rndt(o[0]), rndt(o[1]), rndt(o[2]), rndt(o[3]));
            *(float4*)(dst + 4) =
                make_float4(rndt(o[4]), rndt(o[5]), rndt(o[6]), rndt(o[7]));
        }
    }
}

// ---------------- host launcher ----------------
extern "C" void kernel_launch(void* const* d_in, const int* in_sizes, int n_in,
                              void* d_out, int out_size)
{
    const float* x     = (const float*)d_in[0];
    const float* ln1_g = (const float*)d_in[1];
    const float* ln1_b = (const float*)d_in[2];
    const float* ln2_g = (const float*)d_in[3];
    const float* ln2_b = (const float*)d_in[4];
    const float* w_qkv = (const float*)d_in[5];
    const float* w_out = (const float*)d_in[6];
    const float* rpb   = (const float*)d_in[7];
    const float* ln3_g = (const float*)d_in[8];
    const float* ln3_b = (const float*)d_in[9];
    const float* w1    = (const float*)d_in[10];
    const float* b1    = (const float*)d_in[11];
    const float* w2    = (const float*)d_in[12];
    const float* b2    = (const float*)d_in[13];
    float* out = (float*)d_out;

    float* S = nullptr;
    cudaGetSymbolAddress((void**)&S, g_scratch);

    cudaFuncSetAttribute(k_gemm_mma<0>, cudaFuncAttributeMaxDynamicSharedMemorySize, GEMM_SMEM);
    cudaFuncSetAttribute(k_gemm_mma<1>, cudaFuncAttributeMaxDynamicSharedMemorySize, GEMM_SMEM);
    cudaFuncSetAttribute(k_gemm_mma<2>, cudaFuncAttributeMaxDynamicSharedMemorySize, GEMM_SMEM);
    cudaFuncSetAttribute(k_gemm_mma<3>, cudaFuncAttributeMaxDynamicSharedMemorySize, GEMM_SMEM);
    cudaFuncSetAttribute(k_attn, cudaFuncAttributeMaxDynamicSharedMemorySize, ATTN_SMEM);

    // order chosen so the profiled launch (#4) is the qkv GEMM
    k_gather<<<4096, 256>>>(x);                                              // 1
    k_ln<1><<<4096, 256>>>(S + OFF_XW, S + OFF_T, ln1_g, ln1_b, ln2_g, ln2_b); // 2
    k_transpose<<<dim3(24, 8), 256>>>(w_qkv, S + OFF_BT_QKV, 256, 768);      // 3
    k_gemm_mma<0><<<dim3(6, 1024), 256, GEMM_SMEM>>>(                        // 4
        S + OFF_T, S + OFF_BT_QKV, S + OFF_QKV, S, S, 768, 256);
    k_transpose<<<dim3(8, 8), 256>>>(w_out, S + OFF_BT_OUT, 256, 256);       // 5
    k_transpose<<<dim3(32, 8), 256>>>(w1, S + OFF_BT_W1, 256, 1024);         // 6
    k_transpose<<<dim3(8, 32), 256>>>(w2, S + OFF_BT_W2, 1024, 256);         // 7
    k_attn<<<2048, 256, ATTN_SMEM>>>(rpb);                                   // 8
    k_gemm_mma<1><<<dim3(2, 1024), 256, GEMM_SMEM>>>(
        S + OFF_ATTNO, S + OFF_BT_OUT, S + OFF_XW2, S + OFF_XW, S, 256, 256);
    k_ln<0><<<4096, 256>>>(S + OFF_XW2, S + OFF_F, ln3_g, ln3_b, ln3_g, ln3_b);
    k_gemm_mma<2><<<dim3(8, 1024), 256, GEMM_SMEM>>>(
        S + OFF_F, S + OFF_BT_W1, S + OFF_H, S, b1, 1024, 256);
    k_gemm_mma<3><<<dim3(2, 1024), 256, GEMM_SMEM>>>(
        S + OFF_H, S + OFF_BT_W2, S + OFF_T, S + OFF_XW2, b2, 256, 1024);
    k_scatter<<<4096, 256>>>(out);
}

// round 14
// speedup vs baseline: 1.5394x; 1.3625x over previous
#include <cuda_runtime.h>
#include <cstdint>
#include <cstddef>

#define NTOK 131072
constexpr size_t NT = (size_t)NTOK;
constexpr size_t OFF_XW    = 0;
constexpr size_t OFF_T     = NT * 256;
constexpr size_t OFF_QKV   = NT * 512;
constexpr size_t OFF_ATTNO = NT * 1280;
constexpr size_t OFF_XW2   = NT * 1536;
constexpr size_t OFF_F     = NT * 1792;
constexpr size_t OFF_H     = NT * 2048;
constexpr size_t OFF_BT_QKV = NT * 3072;           // 768x256
constexpr size_t OFF_BT_OUT = OFF_BT_QKV + 196608; // 256x256
constexpr size_t OFF_BT_W1  = OFF_BT_OUT + 65536;  // 1024x256
constexpr size_t OFF_BT_W2  = OFF_BT_W1 + 262144;  // 256x1024
__device__ float g_scratch[OFF_BT_W2 + 262144];

__device__ __forceinline__ float rndt(float x) {   // round to tf32, keep as fp32
    uint32_t u; asm("cvt.rna.tf32.f32 %0, %1;" : "=r"(u) : "f"(x));
    return __uint_as_float(u);
}
__device__ __forceinline__ uint32_t smem_u32(const void* p) {
    uint32_t a;
    asm("{.reg .u64 t; cvta.to.shared.u64 t, %1; cvt.u32.u64 %0, t;}" : "=r"(a) : "l"(p));
    return a;
}
__device__ __forceinline__ void cpa16(uint32_t dst, const float* src) {
    asm volatile("cp.async.ca.shared.global [%0], [%1], 16;" :: "r"(dst), "l"(src));
}
__device__ __forceinline__ void mma8(float* d, const uint32_t* a, const uint32_t* b) {
    asm volatile(
        "mma.sync.aligned.m16n8k8.row.col.f32.tf32.tf32.f32 "
        "{%0,%1,%2,%3},{%4,%5,%6,%7},{%8,%9},{%0,%1,%2,%3};"
        : "+f"(d[0]), "+f"(d[1]), "+f"(d[2]), "+f"(d[3])
        : "r"(a[0]), "r"(a[1]), "r"(a[2]), "r"(a[3]), "r"(b[0]), "r"(b[1]));
}

// ---------------- weight transpose BT[n][k] = round_tf32(B[k][n]) --------
__global__ void __launch_bounds__(256) k_transpose(
    const float* __restrict__ B, float* __restrict__ BT, int K, int N)
{
    __shared__ float t[32][33];
    int kb = blockIdx.y * 32, nb = blockIdx.x * 32;
    int tx = threadIdx.x & 31, ty = threadIdx.x >> 5;
    for (int i = ty; i < 32; i += 8) t[i][tx] = B[(size_t)(kb + i) * N + nb + tx];
    __syncthreads();
    for (int i = ty; i < 32; i += 8) BT[(size_t)(nb + i) * K + kb + tx] = rndt(t[tx][i]);
}

// ---------------- gather / scatter NCHW <-> token-major ----------------
__global__ void __launch_bounds__(256) k_gather(const float* __restrict__ x)
{
    __shared__ float sm[256][33];
    int tid = threadIdx.x, bi = blockIdx.x;
    int dc = bi & 7, w1 = (bi >> 3) & 7, wx = (bi >> 6) & 31, b = bi >> 11;
    const float* xb = x + ((size_t)b * 256 + dc * 32) * 65536 + (size_t)(wx * 8 + w1) * 256;
#pragma unroll
    for (int it = 0; it < 32; ++it) sm[tid][it] = xb[(size_t)it * 65536 + tid];
    __syncthreads();
#pragma unroll
    for (int it = 0; it < 32; ++it) {
        int t = it * 8 + (tid >> 5), dd = tid & 31;
        size_t tok = (((size_t)b * 32 + wx) * 32 + (t >> 3)) * 64 + w1 * 8 + (t & 7);
        g_scratch[OFF_XW + tok * 256 + dc * 32 + dd] = sm[t][dd];
    }
}
__global__ void __launch_bounds__(256) k_scatter(float* __restrict__ out)
{
    __shared__ float sm[256][33];
    int tid = threadIdx.x, bi = blockIdx.x;
    int dc = bi & 7, w1 = (bi >> 3) & 7, wx = (bi >> 6) & 31, b = bi >> 11;
#pragma unroll
    for (int it = 0; it < 32; ++it) {
        int t = it * 8 + (tid >> 5), dd = tid & 31;
        size_t tok = (((size_t)b * 32 + wx) * 32 + (t >> 3)) * 64 + w1 * 8 + (t & 7);
        sm[t][dd] = g_scratch[OFF_T + tok * 256 + dc * 32 + dd];
    }
    __syncthreads();
    float* ob = out + ((size_t)b * 256 + dc * 32) * 65536 + (size_t)(wx * 8 + w1) * 256;
#pragma unroll
    for (int it = 0; it < 32; ++it) ob[(size_t)it * 65536 + tid] = sm[tid][it];
}

// ------- LayerNorm (TWO=1: LN2(LN1(x)); TWO=0: single LN); tf32-rounds out
template <int TWO>
__global__ void __launch_bounds__(256) k_ln(
    const float* __restrict__ src, float* __restrict__ dst,
    const float* __restrict__ g1, const float* __restrict__ b1,
    const float* __restrict__ g2, const float* __restrict__ b2)
{
    __shared__ float sm[8192], sg1[256], sb1[256], sg2[256], sb2[256], st1[32][2], st2[32][2];
    int tid = threadIdx.x;
    size_t base = (size_t)blockIdx.x * 8192;
    sg1[tid] = g1[tid]; sb1[tid] = b1[tid];
    if (TWO) { sg2[tid] = g2[tid]; sb2[tid] = b2[tid]; }
#pragma unroll
    for (int it = 0; it < 32; ++it) sm[it * 256 + tid] = src[base + it * 256 + tid];
    __syncthreads();
    int warp = tid >> 5, lane = tid & 31;
#pragma unroll
    for (int j = 0; j < 4; ++j) {
        int tok = warp * 4 + j;
        float s = 0.f, ss = 0.f;
#pragma unroll
        for (int m = 0; m < 8; ++m) {
            float v = sm[tok * 256 + lane + 32 * m]; s += v; ss += v * v;
        }
#pragma unroll
        for (int o = 16; o > 0; o >>= 1) {
            s += __shfl_xor_sync(~0u, s, o); ss += __shfl_xor_sync(~0u, ss, o);
        }
        float m1 = s * (1.f / 256.f), i1 = rsqrtf(ss * (1.f / 256.f) - m1 * m1 + 1e-5f);
        if (lane == 0) { st1[tok][0] = m1; st1[tok][1] = i1; }
        if (TWO) {
            float s2 = 0.f, ss2 = 0.f;
#pragma unroll
            for (int m = 0; m < 8; ++m) {
                int d = lane + 32 * m;
                float u = (sm[tok * 256 + d] - m1) * i1 * sg1[d] + sb1[d];
                s2 += u; ss2 += u * u;
            }
#pragma unroll
            for (int o = 16; o > 0; o >>= 1) {
                s2 += __shfl_xor_sync(~0u, s2, o); ss2 += __shfl_xor_sync(~0u, ss2, o);
            }
            if (lane == 0) {
                float m2 = s2 * (1.f / 256.f);
                st2[tok][0] = m2; st2[tok][1] = rsqrtf(ss2 * (1.f / 256.f) - m2 * m2 + 1e-5f);
            }
        }
    }
    __syncthreads();
#pragma unroll
    for (int tok = 0; tok < 32; ++tok) {
        float u = (sm[tok * 256 + tid] - st1[tok][0]) * st1[tok][1] * sg1[tid] + sb1[tid];
        if (TWO) u = (u - st2[tok][0]) * st2[tok][1] * sg2[tid] + sb2[tid];
        dst[base + tok * 256 + tid] = rndt(u);
    }
}

// -------- tf32 mma.sync GEMM (exact R10 best config): 128x128, BK=32,
// 8 warps (32x64), 2-stage cp.async.ca, 128-reg cap -> 2 CTAs/SM.
// EPI: 0 none | 1 +RES | 2 round(gelu(+BIAS)) | 3 +BIAS+RES
#define GEMM_SMEM 73728
template <int EPI>
__global__ void __launch_bounds__(256, 2) k_gemm_mma(
    const float* __restrict__ A, const float* __restrict__ BT,
    float* __restrict__ C, const float* __restrict__ RES,
    const float* __restrict__ BIAS, int N, int K)
{
    extern __shared__ float smf[];   // 2 stages x (A[128][36] + B[128][36])
    const int tid = threadIdx.x, lane = tid & 31, wid = tid >> 5;
    const int bm = blockIdx.y << 7, bn = blockIdx.x << 7;
    const int wr = wid & 3, wc = wid >> 2;
    const int g = lane >> 2, q = lane & 3;

    const int lrow = tid >> 3, lkq = (tid & 7) << 2;
    const float* ApG = A  + (size_t)(bm + lrow) * K + lkq;
    const float* BpG = BT + (size_t)(bn + lrow) * K + lkq;
    const uint32_t sBase = smem_u32(smf);
    const uint32_t soff = ((uint32_t)lrow * 36 + (uint32_t)lkq) * 4;

    float acc[2][8][4];
#pragma unroll
    for (int i = 0; i < 2; ++i)
#pragma unroll
        for (int j = 0; j < 8; ++j)
#pragma unroll
            for (int e = 0; e < 4; ++e) acc[i][j][e] = 0.f;

#pragma unroll
    for (int it = 0; it < 4; ++it) {
        cpa16(sBase + soff + it * 32 * 36 * 4, ApG + (size_t)(it * 32) * K);
        cpa16(sBase + 18432u + soff + it * 32 * 36 * 4, BpG + (size_t)(it * 32) * K);
    }
    asm volatile("cp.async.commit_group;" ::: "memory");

    const int nc = K >> 5;
    for (int c = 0; c < nc; ++c) {
        if (c + 1 < nc) {
            const int kc = (c + 1) << 5;
            const uint32_t st = sBase + (uint32_t)((c + 1) & 1) * 36864u;
#pragma unroll
            for (int it = 0; it < 4; ++it) {
                cpa16(st + soff + it * 32 * 36 * 4, ApG + (size_t)(it * 32) * K + kc);
                cpa16(st + 18432u + soff + it * 32 * 36 * 4, BpG + (size_t)(it * 32) * K + kc);
            }
            asm volatile("cp.async.commit_group;" ::: "memory");
            asm volatile("cp.async.wait_group 1;" ::: "memory");
        } else {
            asm volatile("cp.async.wait_group 0;" ::: "memory");
        }
        __syncthreads();

        const uint32_t* Ab = (const uint32_t*)(smf + (c & 1) * 9216) + (wr << 5) * 36;
        const uint32_t* Bb = (const uint32_t*)(smf + (c & 1) * 9216 + 4608) + (wc << 6) * 36;
#pragma unroll
        for (int ks = 0; ks < 4; ++ks) {
            const int kb = ks << 3;
            uint32_t af[2][4];
#pragma unroll
            for (int mt = 0; mt < 2; ++mt) {
                af[mt][0] = Ab[(mt * 16 + g) * 36 + kb + q];
                af[mt][1] = Ab[(mt * 16 + 8 + g) * 36 + kb + q];
                af[mt][2] = Ab[(mt * 16 + g) * 36 + kb + 4 + q];
                af[mt][3] = Ab[(mt * 16 + 8 + g) * 36 + kb + 4 + q];
            }
#pragma unroll
            for (int nt = 0; nt < 8; ++nt) {
                uint32_t bf[2];
                bf[0] = Bb[(nt * 8 + g) * 36 + kb + q];
                bf[1] = Bb[(nt * 8 + g) * 36 + kb + 4 + q];
                mma8(acc[0][nt], af[0], bf);
                mma8(acc[1][nt], af[1], bf);
            }
        }
        __syncthreads();
    }

#pragma unroll
    for (int mt = 0; mt < 2; ++mt) {
#pragma unroll
        for (int nt = 0; nt < 8; ++nt) {
            int row0 = bm + (wr << 5) + mt * 16 + g;
            int col  = bn + (wc << 6) + nt * 8 + q * 2;
            float v00 = acc[mt][nt][0], v01 = acc[mt][nt][1];
            float v10 = acc[mt][nt][2], v11 = acc[mt][nt][3];
            if (EPI == 2 || EPI == 3) {
                float2 bb = *(const float2*)(BIAS + col);
                v00 += bb.x; v01 += bb.y; v10 += bb.x; v11 += bb.y;
            }
            if (EPI == 1 || EPI == 3) {
                float2 r0 = *(const float2*)(RES + (size_t)row0 * N + col);
                float2 r1 = *(const float2*)(RES + (size_t)(row0 + 8) * N + col);
                v00 += r0.x; v01 += r0.y; v10 += r1.x; v11 += r1.y;
            }
            if (EPI == 2) {
                v00 = rndt(v00 * normcdff(v00)); v01 = rndt(v01 * normcdff(v01));
                v10 = rndt(v10 * normcdff(v10)); v11 = rndt(v11 * normcdff(v11));
            }
            *(float2*)(C + (size_t)row0 * N + col)       = make_float2(v00, v01);
            *(float2*)(C + (size_t)(row0 + 8) * N + col) = make_float2(v10, v11);
        }
    }
}

// -------- windowed attention via mma.sync (tensor cores) ----------------
// One CTA per window. 8 warps; 2 heads per pass (4 warps/head, 16-row slices).
// S = Q.K^T (m16n8k8), bias+softmax in acc layout, P->smem, O = P.V (mma).
// smem floats: sQ 2x64x36 | sK 2x64x36 | sVt 2x32x68 | sP 2x64x68 | srpb 1800
#define ATTN_SMEM 96288
__global__ void __launch_bounds__(256) k_attn(const float* __restrict__ rpb)
{
    extern __shared__ float sa[];
    float* sQ  = sa;            // [lh*2304 + t*36 + d]
    float* sK  = sa + 4608;     // [lh*2304 + t*36 + d]
    float* sVt = sa + 9216;     // [lh*2176 + d*68 + t]
    float* sP  = sa + 13568;    // [lh*4352 + r*68 + c]
    float* srpb = sa + 22272;   // [1800]

    const int tid = threadIdx.x, lane = tid & 31, wid = tid >> 5;
    const int g = lane >> 2, q = lane & 3;
    const int hh = wid >> 2, slice = (wid & 3) << 4;
    const size_t tokbase = (size_t)blockIdx.x * 64;
    const float* qkv = g_scratch + OFF_QKV;
    float* outp = g_scratch + OFF_ATTNO;
    for (int i = tid; i < 1800; i += 256) srpb[i] = rpb[i];
    const float sc = 0.17677669529663687f;

    for (int h = 0; h < 8; h += 2) {
        __syncthreads();   // protect smem reuse (incl. srpb fill on pass 0)
        // ---- load Q,K (row-major) and V (transposed) for heads h,h+1 ----
#pragma unroll
        for (int m = 0; m < 4; ++m) {
            int e = m * 256 + tid;
            int t = e >> 4, rem = e & 15;
            int lh = rem >> 3, d4 = (rem & 7) << 2;
            const float* src = qkv + (tokbase + t) * 768 + (h + lh) * 32 + d4;
            float4 q4 = *(const float4*)src;
            float4 k4 = *(const float4*)(src + 256);
            float4 v4 = *(const float4*)(src + 512);
            float* dq = sQ + lh * 2304 + t * 36 + d4;
            dq[0] = rndt(q4.x * sc); dq[1] = rndt(q4.y * sc);
            dq[2] = rndt(q4.z * sc); dq[3] = rndt(q4.w * sc);
            float* dk = sK + lh * 2304 + t * 36 + d4;
            dk[0] = rndt(k4.x); dk[1] = rndt(k4.y);
            dk[2] = rndt(k4.z); dk[3] = rndt(k4.w);
            float* dv = sVt + lh * 2176 + t;
            dv[(d4 + 0) * 68] = rndt(v4.x); dv[(d4 + 1) * 68] = rndt(v4.y);
            dv[(d4 + 2) * 68] = rndt(v4.z); dv[(d4 + 3) * 68] = rndt(v4.w);
        }
        __syncthreads();

        // ---- S = Q.K^T for this warp's 16-row slice of head h+hh ----
        const float* Q = sQ + hh * 2304;
        const float* K = sK + hh * 2304;
        float accs[8][4];
#pragma unroll
        for (int nt = 0; nt < 8; ++nt)
#pragma unroll
            for (int e = 0; e < 4; ++e) accs[nt][e] = 0.f;
#pragma unroll
        for (int kt = 0; kt < 4; ++kt) {
            const int kb = kt << 3;
            uint32_t af[4];
            af[0] = __float_as_uint(Q[(slice + g) * 36 + kb + q]);
            af[1] = __float_as_uint(Q[(slice + 8 + g) * 36 + kb + q]);
            af[2] = __float_as_uint(Q[(slice + g) * 36 + kb + 4 + q]);
            af[3] = __float_as_uint(Q[(slice + 8 + g) * 36 + kb + 4 + q]);
#pragma unroll
            for (int nt = 0; nt < 8; ++nt) {
                uint32_t bf[2];
                bf[0] = __float_as_uint(K[(nt * 8 + g) * 36 + kb + q]);
                bf[1] = __float_as_uint(K[(nt * 8 + g) * 36 + kb + 4 + q]);
                mma8(accs[nt], af, bf);
            }
        }

        // ---- + relative position bias (acc layout: rows r0,r0+8; cols nt*8+2q+j)
        const int r0 = slice + g, r1 = r0 + 8;
        const int ri0 = r0 >> 3, rj0 = r0 & 7, ri1 = r1 >> 3, rj1 = r1 & 7;
#pragma unroll
        for (int nt = 0; nt < 8; ++nt) {
            int c0 = nt * 8 + 2 * q, c1 = c0 + 1;
            int ci0 = c0 >> 3, cj0 = c0 & 7, ci1 = c1 >> 3, cj1 = c1 & 7;
            accs[nt][0] += srpb[((ri0 - ci0 + 7) * 15 + (rj0 - cj0 + 7)) * 8 + h + hh];
            accs[nt][1] += srpb[((ri0 - ci1 + 7) * 15 + (rj0 - cj1 + 7)) * 8 + h + hh];
            accs[nt][2] += srpb[((ri1 - ci0 + 7) * 15 + (rj1 - cj0 + 7)) * 8 + h + hh];
            accs[nt][3] += srpb[((ri1 - ci1 + 7) * 15 + (rj1 - cj1 + 7)) * 8 + h + hh];
        }

        // ---- softmax per row (full row lives in this quad: q=0..3) ----
        float mx0 = accs[0][0], mx1 = accs[0][2];
#pragma unroll
        for (int nt = 0; nt < 8; ++nt) {
            mx0 = fmaxf(mx0, fmaxf(accs[nt][0], accs[nt][1]));
            mx1 = fmaxf(mx1, fmaxf(accs[nt][2], accs[nt][3]));
        }
        mx0 = fmaxf(mx0, __shfl_xor_sync(~0u, mx0, 1));
        mx0 = fmaxf(mx0, __shfl_xor_sync(~0u, mx0, 2));
        mx1 = fmaxf(mx1, __shfl_xor_sync(~0u, mx1, 1));
        mx1 = fmaxf(mx1, __shfl_xor_sync(~0u, mx1, 2));
        float sum0 = 0.f, sum1 = 0.f;
#pragma unroll
        for (int nt = 0; nt < 8; ++nt) {
            accs[nt][0] = __expf(accs[nt][0] - mx0); sum0 += accs[nt][0];
            accs[nt][1] = __expf(accs[nt][1] - mx0); sum0 += accs[nt][1];
            accs[nt][2] = __expf(accs[nt][2] - mx1); sum1 += accs[nt][2];
            accs[nt][3] = __expf(accs[nt][3] - mx1); sum1 += accs[nt][3];
        }
        sum0 += __shfl_xor_sync(~0u, sum0, 1); sum0 += __shfl_xor_sync(~0u, sum0, 2);
        sum1 += __shfl_xor_sync(~0u, sum1, 1); sum1 += __shfl_xor_sync(~0u, sum1, 2);
        float inv0 = 1.f / sum0, inv1 = 1.f / sum1;

        float* P = sP + hh * 4352;
#pragma unroll
        for (int nt = 0; nt < 8; ++nt) {
            int c0 = nt * 8 + 2 * q;
            P[r0 * 68 + c0]     = rndt(accs[nt][0] * inv0);
            P[r0 * 68 + c0 + 1] = rndt(accs[nt][1] * inv0);
            P[r1 * 68 + c0]     = rndt(accs[nt][2] * inv1);
            P[r1 * 68 + c0 + 1] = rndt(accs[nt][3] * inv1);
        }
        __syncthreads();   // all warps of the head must finish P before PV

        // ---- O = P.V (A = P[64 rows][64 k], B^T = Vt[32 n][64 k]) ----
        const float* Vt = sVt + hh * 2176;
        float acco[4][4];
#pragma unroll
        for (int nt = 0; nt < 4; ++nt)
#pragma unroll
            for (int e = 0; e < 4; ++e) acco[nt][e] = 0.f;
#pragma unroll
        for (int kt = 0; kt < 8; ++kt) {
            const int kb = kt << 3;
            uint32_t af[4];
            af[0] = __float_as_uint(P[(slice + g) * 68 + kb + q]);
            af[1] = __float_as_uint(P[(slice + 8 + g) * 68 + kb + q]);
            af[2] = __float_as_uint(P[(slice + g) * 68 + kb + 4 + q]);
            af[3] = __float_as_uint(P[(slice + 8 + g) * 68 + kb + 4 + q]);
#pragma unroll
            for (int nt = 0; nt < 4; ++nt) {
                uint32_t bf[2];
                bf[0] = __float_as_uint(Vt[(nt * 8 + g) * 68 + kb + q]);
                bf[1] = __float_as_uint(Vt[(nt * 8 + g) * 68 + kb + 4 + q]);
                mma8(acco[nt], af, bf);
            }
        }
#pragma unroll
        for (int nt = 0; nt < 4; ++nt) {
            int col = nt * 8 + 2 * q;
            float* d0 = outp + (tokbase + r0) * 256 + (h + hh) * 32 + col;
            float* d1 = outp + (tokbase + r1) * 256 + (h + hh) * 32 + col;
            *(float2*)d0 = make_float2(rndt(acco[nt][0]), rndt(acco[nt][1]));
            *(float2*)d1 = make_float2(rndt(acco[nt][2]), rndt(acco[nt][3]));
        }
    }
}

// ---------------- host launcher ----------------
extern "C" void kernel_launch(void* const* d_in, const int* in_sizes, int n_in,
                              void* d_out, int out_size)
{
    const float* x     = (const float*)d_in[0];
    const float* ln1_g = (const float*)d_in[1];
    const float* ln1_b = (const float*)d_in[2];
    const float* ln2_g = (const float*)d_in[3];
    const float* ln2_b = (const float*)d_in[4];
    const float* w_qkv = (const float*)d_in[5];
    const float* w_out = (const float*)d_in[6];
    const float* rpb   = (const float*)d_in[7];
    const float* ln3_g = (const float*)d_in[8];
    const float* ln3_b = (const float*)d_in[9];
    const float* w1    = (const float*)d_in[10];
    const float* b1    = (const float*)d_in[11];
    const float* w2    = (const float*)d_in[12];
    const float* b2    = (const float*)d_in[13];
    float* out = (float*)d_out;

    float* S = nullptr;
    cudaGetSymbolAddress((void**)&S, g_scratch);

    cudaFuncSetAttribute(k_gemm_mma<0>, cudaFuncAttributeMaxDynamicSharedMemorySize, GEMM_SMEM);
    cudaFuncSetAttribute(k_gemm_mma<1>, cudaFuncAttributeMaxDynamicSharedMemorySize, GEMM_SMEM);
    cudaFuncSetAttribute(k_gemm_mma<2>, cudaFuncAttributeMaxDynamicSharedMemorySize, GEMM_SMEM);
    cudaFuncSetAttribute(k_gemm_mma<3>, cudaFuncAttributeMaxDynamicSharedMemorySize, GEMM_SMEM);
    cudaFuncSetAttribute(k_attn, cudaFuncAttributeMaxDynamicSharedMemorySize, ATTN_SMEM);

    k_gather<<<4096, 256>>>(x);                                              // 1
    k_ln<1><<<4096, 256>>>(S + OFF_XW, S + OFF_T, ln1_g, ln1_b, ln2_g, ln2_b); // 2
    k_transpose<<<dim3(24, 8), 256>>>(w_qkv, S + OFF_BT_QKV, 256, 768);      // 3
    k_gemm_mma<0><<<dim3(6, 1024), 256, GEMM_SMEM>>>(                        // 4
        S + OFF_T, S + OFF_BT_QKV, S + OFF_QKV, S, S, 768, 256);
    k_transpose<<<dim3(8, 8), 256>>>(w_out, S + OFF_BT_OUT, 256, 256);       // 5
    k_transpose<<<dim3(32, 8), 256>>>(w1, S + OFF_BT_W1, 256, 1024);         // 6
    k_transpose<<<dim3(8, 32), 256>>>(w2, S + OFF_BT_W2, 1024, 256);         // 7
    k_attn<<<2048, 256, ATTN_SMEM>>>(rpb);                                   // 8
    k_gemm_mma<1><<<dim3(2, 1024), 256, GEMM_SMEM>>>(
        S + OFF_ATTNO, S + OFF_BT_OUT, S + OFF_XW2, S + OFF_XW, S, 256, 256);
    k_ln<0><<<4096, 256>>>(S + OFF_XW2, S + OFF_F, ln3_g, ln3_b, ln3_g, ln3_b);
    k_gemm_mma<2><<<dim3(8, 1024), 256, GEMM_SMEM>>>(
        S + OFF_F, S + OFF_BT_W1, S + OFF_H, S, b1, 1024, 256);
    k_gemm_mma<3><<<dim3(2, 1024), 256, GEMM_SMEM>>>(
        S + OFF_H, S + OFF_BT_W2, S + OFF_T, S + OFF_XW2, b2, 256, 1024);
    k_scatter<<<4096, 256>>>(out);
}